// round 2
// baseline (speedup 1.0000x reference)
#include <cuda_runtime.h>
#include <math_constants.h>

#define L 1024
#define CS 256
#define CZ 128
#define NH 8
#define DH 32
#define LN_EPS 1e-5f
#define QK_SCALE 0.17677669529663687f  // 1/sqrt(32)

// ---------------- scratch (device globals; no allocation allowed) ----------------
__device__ float d_sln[L * CS];
__device__ float d_Q[L * CS];
__device__ float d_K[L * CS];
__device__ float d_V[L * CS];
__device__ float d_G[L * CS];
__device__ float d_Bt[(size_t)L * NH * L];   // bias transposed: [i][h][j], 32 MB
__device__ float d_AO[L * CS];               // G * attn_out

// ---------------- Kernel 1: LayerNorm(s) ----------------
__global__ __launch_bounds__(256) void ln_s_kernel(const float* __restrict__ s,
                                                   const float* __restrict__ g,
                                                   const float* __restrict__ b) {
    int r = blockIdx.x, t = threadIdx.x;
    float v = s[r * CS + t];
    __shared__ float red[8];

    float sum = v;
#pragma unroll
    for (int off = 16; off > 0; off >>= 1) sum += __shfl_xor_sync(0xffffffffu, sum, off);
    if ((t & 31) == 0) red[t >> 5] = sum;
    __syncthreads();
    float tot = 0.f;
#pragma unroll
    for (int k = 0; k < 8; k++) tot += red[k];
    float mean = tot * (1.f / CS);
    float d = v - mean;
    __syncthreads();

    float sq = d * d;
#pragma unroll
    for (int off = 16; off > 0; off >>= 1) sq += __shfl_xor_sync(0xffffffffu, sq, off);
    if ((t & 31) == 0) red[t >> 5] = sq;
    __syncthreads();
    float tot2 = 0.f;
#pragma unroll
    for (int k = 0; k < 8; k++) tot2 += red[k];
    float rstd = rsqrtf(tot2 * (1.f / CS) + LN_EPS);

    d_sln[r * CS + t] = d * rstd * g[t] + b[t];
}

// ---------------- shared GEMM tile helper: C[64x64] tile of (A[1024x256] @ B[256x256]) ----------------
// 256 threads, each computes 4x4 micro-tile.
__device__ __forceinline__ void gemm_tile_64x64(const float* __restrict__ A,
                                                const float* __restrict__ Bm,
                                                int m0, int n0, float acc[4][4]) {
    __shared__ float As[64][33];
    __shared__ float Bs[32][65];
    int t = threadIdx.x;
    int tx = t & 15, ty = t >> 4;

    for (int k0 = 0; k0 < 256; k0 += 32) {
        int ra = t >> 2, ca = (t & 3) * 8;
#pragma unroll
        for (int q = 0; q < 8; q++) As[ra][ca + q] = A[(m0 + ra) * 256 + k0 + ca + q];
        int rb = t >> 3, cb = (t & 7) * 8;
#pragma unroll
        for (int q = 0; q < 8; q++) Bs[rb][cb + q] = Bm[(k0 + rb) * 256 + n0 + cb + q];
        __syncthreads();
#pragma unroll 8
        for (int kk = 0; kk < 32; kk++) {
            float a[4], bb[4];
#pragma unroll
            for (int ii = 0; ii < 4; ii++) a[ii] = As[ty * 4 + ii][kk];
#pragma unroll
            for (int jj = 0; jj < 4; jj++) bb[jj] = Bs[kk][tx * 4 + jj];
#pragma unroll
            for (int ii = 0; ii < 4; ii++)
#pragma unroll
                for (int jj = 0; jj < 4; jj++) acc[ii][jj] = fmaf(a[ii], bb[jj], acc[ii][jj]);
        }
        __syncthreads();
    }
}

// ---------------- Kernel 2: QKVG projections ----------------
__global__ __launch_bounds__(256) void gemm_qkvg_kernel(const float* __restrict__ Wq,
                                                        const float* __restrict__ bq,
                                                        const float* __restrict__ Wk,
                                                        const float* __restrict__ Wv,
                                                        const float* __restrict__ Wg) {
    const float* Bm;
    float* C;
    int mode;
    switch (blockIdx.z) {
        case 0: Bm = Wq; C = d_Q; mode = 1; break;
        case 1: Bm = Wk; C = d_K; mode = 0; break;
        case 2: Bm = Wv; C = d_V; mode = 0; break;
        default: Bm = Wg; C = d_G; mode = 2; break;
    }
    int m0 = blockIdx.x * 64, n0 = blockIdx.y * 64;
    float acc[4][4] = {};
    gemm_tile_64x64(d_sln, Bm, m0, n0, acc);

    int tx = threadIdx.x & 15, ty = threadIdx.x >> 4;
#pragma unroll
    for (int ii = 0; ii < 4; ii++)
#pragma unroll
        for (int jj = 0; jj < 4; jj++) {
            int mI = m0 + ty * 4 + ii, nI = n0 + tx * 4 + jj;
            float v = acc[ii][jj];
            if (mode == 1) v += bq[nI];
            if (mode == 2) v = 1.f / (1.f + __expf(-v));
            C[mI * 256 + nI] = v;
        }
}

// ---------------- Kernel 3: LayerNorm(z) fused with @Wb -> Bt[i][h][j] ----------------
// grid (1024, 8), block 256 = 8 warps; each warp handles 16 (i,j) pairs.
__global__ __launch_bounds__(256) void zln_bias_kernel(const float* __restrict__ z,
                                                       const float* __restrict__ gz,
                                                       const float* __restrict__ bz,
                                                       const float* __restrict__ Wb) {
    __shared__ float Wbs[CZ * NH];  // 4 KB
    __shared__ float gzs[CZ], bzs[CZ];
    int t = threadIdx.x;
    for (int idx = t; idx < CZ * NH; idx += 256) Wbs[idx] = Wb[idx];
    if (t < CZ) { gzs[t] = gz[t]; bzs[t] = bz[t]; }
    __syncthreads();

    int warp = t >> 5, lane = t & 31;
    int i = blockIdx.x;
    size_t bti = (size_t)i * (NH * L);

    for (int it = 0; it < 16; it++) {
        int j = blockIdx.y * 128 + warp * 16 + it;
        const float4 zv = *(const float4*)&z[((size_t)i * L + j) * CZ + lane * 4];
        float s1 = zv.x + zv.y + zv.z + zv.w;
        float s2 = zv.x * zv.x + zv.y * zv.y + zv.z * zv.z + zv.w * zv.w;
#pragma unroll
        for (int off = 16; off > 0; off >>= 1) {
            s1 += __shfl_xor_sync(0xffffffffu, s1, off);
            s2 += __shfl_xor_sync(0xffffffffu, s2, off);
        }
        float mean = s1 * (1.f / CZ);
        float var = s2 * (1.f / CZ) - mean * mean;
        float rstd = rsqrtf(var + LN_EPS);

        int c0 = lane * 4;
        float zn[4];
        zn[0] = (zv.x - mean) * rstd * gzs[c0 + 0] + bzs[c0 + 0];
        zn[1] = (zv.y - mean) * rstd * gzs[c0 + 1] + bzs[c0 + 1];
        zn[2] = (zv.z - mean) * rstd * gzs[c0 + 2] + bzs[c0 + 2];
        zn[3] = (zv.w - mean) * rstd * gzs[c0 + 3] + bzs[c0 + 3];

        float a0 = 0, a1 = 0, a2 = 0, a3 = 0, a4 = 0, a5 = 0, a6 = 0, a7 = 0;
#pragma unroll
        for (int c = 0; c < 4; c++) {
            const float* wrow = &Wbs[(c0 + c) * NH];
            a0 = fmaf(zn[c], wrow[0], a0);
            a1 = fmaf(zn[c], wrow[1], a1);
            a2 = fmaf(zn[c], wrow[2], a2);
            a3 = fmaf(zn[c], wrow[3], a3);
            a4 = fmaf(zn[c], wrow[4], a4);
            a5 = fmaf(zn[c], wrow[5], a5);
            a6 = fmaf(zn[c], wrow[6], a6);
            a7 = fmaf(zn[c], wrow[7], a7);
        }
#pragma unroll
        for (int off = 16; off > 0; off >>= 1) {
            a0 += __shfl_xor_sync(0xffffffffu, a0, off);
            a1 += __shfl_xor_sync(0xffffffffu, a1, off);
            a2 += __shfl_xor_sync(0xffffffffu, a2, off);
            a3 += __shfl_xor_sync(0xffffffffu, a3, off);
            a4 += __shfl_xor_sync(0xffffffffu, a4, off);
            a5 += __shfl_xor_sync(0xffffffffu, a5, off);
            a6 += __shfl_xor_sync(0xffffffffu, a6, off);
            a7 += __shfl_xor_sync(0xffffffffu, a7, off);
        }
        if (lane == 0) d_Bt[bti + 0 * L + j] = a0;
        if (lane == 1) d_Bt[bti + 1 * L + j] = a1;
        if (lane == 2) d_Bt[bti + 2 * L + j] = a2;
        if (lane == 3) d_Bt[bti + 3 * L + j] = a3;
        if (lane == 4) d_Bt[bti + 4 * L + j] = a4;
        if (lane == 5) d_Bt[bti + 5 * L + j] = a5;
        if (lane == 6) d_Bt[bti + 6 * L + j] = a6;
        if (lane == 7) d_Bt[bti + 7 * L + j] = a7;
    }
}

// ---------------- Kernel 4: attention (flash-style), BM=32 rows per block, 128 threads ----------------
__global__ __launch_bounds__(128) void attn_kernel(const int* __restrict__ mask) {
    __shared__ float Qs[32][33];
    __shared__ float Ks[64][33];
    __shared__ float Vs[64][32];
    __shared__ float Ss[32][65];
    __shared__ unsigned char ms[64];

    int t = threadIdx.x;
    int h = blockIdx.y;
    int i0 = blockIdx.x * 32;
    int tx = t & 15, ty = t >> 4;     // S-compute mapping (16 x 8)
    int rw = t >> 2, gq = t & 3;      // softmax / PV mapping (32 rows x 4)
    int dbase = gq * 8;

    // load Q (pre-scaled)
    {
        int r = t >> 2, c = (t & 3) * 8;
#pragma unroll
        for (int q = 0; q < 8; q++)
            Qs[r][c + q] = d_Q[(i0 + r) * CS + h * DH + c + q] * QK_SCALE;
    }

    float m = -CUDART_INF_F, l = 0.f;
    float O[8] = {};

    for (int jt = 0; jt < 16; jt++) {
        int j0 = jt * 64;
        __syncthreads();
        // load K/V tiles (64 x 32 each), 16 floats per thread
        {
            int r = t >> 1, c = (t & 1) * 16;
#pragma unroll
            for (int q = 0; q < 16; q++) {
                Ks[r][c + q] = d_K[(j0 + r) * CS + h * DH + c + q];
                Vs[r][c + q] = d_V[(j0 + r) * CS + h * DH + c + q];
            }
        }
        if (t < 64) ms[t] = (unsigned char)(mask[j0 + t] != 0);
        __syncthreads();

        // S = Q K^T tile (32 x 64)
        float sacc[4][4] = {};
#pragma unroll 8
        for (int d = 0; d < 32; d++) {
            float a[4], bb[4];
#pragma unroll
            for (int ii = 0; ii < 4; ii++) a[ii] = Qs[ty * 4 + ii][d];
#pragma unroll
            for (int jj = 0; jj < 4; jj++) bb[jj] = Ks[tx * 4 + jj][d];
#pragma unroll
            for (int ii = 0; ii < 4; ii++)
#pragma unroll
                for (int jj = 0; jj < 4; jj++) sacc[ii][jj] = fmaf(a[ii], bb[jj], sacc[ii][jj]);
        }
        // add bias, apply mask, store to smem
#pragma unroll
        for (int ii = 0; ii < 4; ii++) {
            int iI = ty * 4 + ii;
            const float4 bv = *(const float4*)&d_Bt[(size_t)(i0 + iI) * (NH * L) + h * L + j0 + tx * 4];
            float bb4[4] = {bv.x, bv.y, bv.z, bv.w};
#pragma unroll
            for (int jj = 0; jj < 4; jj++) {
                int jl = tx * 4 + jj;
                Ss[iI][jl] = ms[jl] ? (sacc[ii][jj] + bb4[jj]) : -CUDART_INF_F;
            }
        }
        __syncthreads();

        // online softmax on row rw, segment [gq*16, gq*16+16)
        float mx = -CUDART_INF_F;
#pragma unroll
        for (int q = 0; q < 16; q++) mx = fmaxf(mx, Ss[rw][gq * 16 + q]);
        mx = fmaxf(mx, __shfl_xor_sync(0xffffffffu, mx, 1));
        mx = fmaxf(mx, __shfl_xor_sync(0xffffffffu, mx, 2));
        float nm = fmaxf(m, mx);
        float alpha = (nm == -CUDART_INF_F) ? 1.f : __expf(m - nm);
        float ps = 0.f;
#pragma unroll
        for (int q = 0; q < 16; q++) {
            float sv = Ss[rw][gq * 16 + q];
            float p = (sv == -CUDART_INF_F) ? 0.f : __expf(sv - nm);
            Ss[rw][gq * 16 + q] = p;
            ps += p;
        }
        ps += __shfl_xor_sync(0xffffffffu, ps, 1);
        ps += __shfl_xor_sync(0xffffffffu, ps, 2);
        l = l * alpha + ps;
        m = nm;
#pragma unroll
        for (int k = 0; k < 8; k++) O[k] *= alpha;
        __syncwarp();

        // O += P @ V
#pragma unroll 4
        for (int j = 0; j < 64; j++) {
            float p = Ss[rw][j];
            const float4 v0 = *(const float4*)&Vs[j][dbase];
            const float4 v1 = *(const float4*)&Vs[j][dbase + 4];
            O[0] = fmaf(p, v0.x, O[0]);
            O[1] = fmaf(p, v0.y, O[1]);
            O[2] = fmaf(p, v0.z, O[2]);
            O[3] = fmaf(p, v0.w, O[3]);
            O[4] = fmaf(p, v1.x, O[4]);
            O[5] = fmaf(p, v1.y, O[5]);
            O[6] = fmaf(p, v1.z, O[6]);
            O[7] = fmaf(p, v1.w, O[7]);
        }
        __syncwarp();
    }

    float rl = (l > 0.f) ? (1.f / l) : 0.f;
    int base = (i0 + rw) * CS + h * DH + dbase;
#pragma unroll
    for (int q = 0; q < 8; q++) d_AO[base + q] = O[q] * rl * d_G[base + q];
}

// ---------------- Kernel 5: ds = (G*out) @ Wo * mask ----------------
__global__ __launch_bounds__(256) void gemm_out_kernel(const float* __restrict__ Wo,
                                                       const int* __restrict__ mask,
                                                       float* __restrict__ out) {
    int m0 = blockIdx.x * 64, n0 = blockIdx.y * 64;
    float acc[4][4] = {};
    gemm_tile_64x64(d_AO, Wo, m0, n0, acc);

    int tx = threadIdx.x & 15, ty = threadIdx.x >> 4;
#pragma unroll
    for (int ii = 0; ii < 4; ii++) {
        int mI = m0 + ty * 4 + ii;
        float mk = (mask[mI] != 0) ? 1.f : 0.f;
#pragma unroll
        for (int jj = 0; jj < 4; jj++) {
            int nI = n0 + tx * 4 + jj;
            out[mI * 256 + nI] = acc[ii][jj] * mk;
        }
    }
}

// ---------------- launch ----------------
extern "C" void kernel_launch(void* const* d_in, const int* in_sizes, int n_in,
                              void* d_out, int out_size) {
    const float* s = (const float*)d_in[0];
    const float* z = (const float*)d_in[1];
    const int* res_mask = (const int*)d_in[2];
    const float* g_s = (const float*)d_in[3];
    const float* b_s = (const float*)d_in[4];
    const float* g_z = (const float*)d_in[5];
    const float* b_z = (const float*)d_in[6];
    const float* Wq = (const float*)d_in[7];
    const float* bq = (const float*)d_in[8];
    const float* Wk = (const float*)d_in[9];
    const float* Wv = (const float*)d_in[10];
    const float* Wb = (const float*)d_in[11];
    const float* Wg = (const float*)d_in[12];
    const float* Wo = (const float*)d_in[13];
    float* out = (float*)d_out;

    ln_s_kernel<<<L, 256>>>(s, g_s, b_s);
    gemm_qkvg_kernel<<<dim3(16, 4, 4), 256>>>(Wq, bq, Wk, Wv, Wg);
    zln_bias_kernel<<<dim3(L, 8), 256>>>(z, g_z, b_z, Wb);
    attn_kernel<<<dim3(32, 8), 128>>>(res_mask);
    gemm_out_kernel<<<dim3(16, 4), 256>>>(Wo, res_mask, out);
}

// round 3
// speedup vs baseline: 3.3542x; 3.3542x over previous
#include <cuda_runtime.h>
#include <math_constants.h>

#define L 1024
#define CS 256
#define CZ 128
#define NH 8
#define DH 32
#define NSPLIT 4
#define LN_EPS 1e-5f
#define QK_SCALE 0.17677669529663687f  // 1/sqrt(32)

// ---------------- scratch (device globals; no allocation allowed) ----------------
__device__ float d_sln[L * CS];
__device__ float d_Q[L * CS];
__device__ float d_K[L * CS];
__device__ float d_V[L * CS];
__device__ float d_G[L * CS];
__device__ float d_Bt[(size_t)L * NH * L];             // bias transposed: [i][h][j], 32 MB
__device__ float d_AO[L * CS];                         // G * attn_out
__device__ float d_pO[NSPLIT * NH * L * DH];           // split attention partial O
__device__ float2 d_pml[NSPLIT * NH * L];              // split attention partial (m, l)

// ---------------- Kernel 1: LayerNorm(s) ----------------
__global__ __launch_bounds__(256) void ln_s_kernel(const float* __restrict__ s,
                                                   const float* __restrict__ g,
                                                   const float* __restrict__ b) {
    int r = blockIdx.x, t = threadIdx.x;
    float v = s[r * CS + t];
    __shared__ float red[8];

    float sum = v;
#pragma unroll
    for (int off = 16; off > 0; off >>= 1) sum += __shfl_xor_sync(0xffffffffu, sum, off);
    if ((t & 31) == 0) red[t >> 5] = sum;
    __syncthreads();
    float tot = 0.f;
#pragma unroll
    for (int k = 0; k < 8; k++) tot += red[k];
    float mean = tot * (1.f / CS);
    float d = v - mean;
    __syncthreads();

    float sq = d * d;
#pragma unroll
    for (int off = 16; off > 0; off >>= 1) sq += __shfl_xor_sync(0xffffffffu, sq, off);
    if ((t & 31) == 0) red[t >> 5] = sq;
    __syncthreads();
    float tot2 = 0.f;
#pragma unroll
    for (int k = 0; k < 8; k++) tot2 += red[k];
    float rstd = rsqrtf(tot2 * (1.f / CS) + LN_EPS);

    d_sln[r * CS + t] = d * rstd * g[t] + b[t];
}

// ---------------- shared GEMM tile helper: C[64x64] tile of (A[1024x256] @ B[256x256]) ----------------
__device__ __forceinline__ void gemm_tile_64x64(const float* __restrict__ A,
                                                const float* __restrict__ Bm,
                                                int m0, int n0, float acc[4][4]) {
    __shared__ float As[64][33];
    __shared__ float Bs[32][65];
    int t = threadIdx.x;
    int tx = t & 15, ty = t >> 4;

    for (int k0 = 0; k0 < 256; k0 += 32) {
        int ra = t >> 2, ca = (t & 3) * 8;
#pragma unroll
        for (int q = 0; q < 8; q++) As[ra][ca + q] = A[(m0 + ra) * 256 + k0 + ca + q];
        int rb = t >> 3, cb = (t & 7) * 8;
#pragma unroll
        for (int q = 0; q < 8; q++) Bs[rb][cb + q] = Bm[(k0 + rb) * 256 + n0 + cb + q];
        __syncthreads();
#pragma unroll 8
        for (int kk = 0; kk < 32; kk++) {
            float a[4], bb[4];
#pragma unroll
            for (int ii = 0; ii < 4; ii++) a[ii] = As[ty * 4 + ii][kk];
#pragma unroll
            for (int jj = 0; jj < 4; jj++) bb[jj] = Bs[kk][tx * 4 + jj];
#pragma unroll
            for (int ii = 0; ii < 4; ii++)
#pragma unroll
                for (int jj = 0; jj < 4; jj++) acc[ii][jj] = fmaf(a[ii], bb[jj], acc[ii][jj]);
        }
        __syncthreads();
    }
}

// ---------------- Kernel 2: QKVG projections ----------------
__global__ __launch_bounds__(256) void gemm_qkvg_kernel(const float* __restrict__ Wq,
                                                        const float* __restrict__ bq,
                                                        const float* __restrict__ Wk,
                                                        const float* __restrict__ Wv,
                                                        const float* __restrict__ Wg) {
    const float* Bm;
    float* C;
    int mode;
    switch (blockIdx.z) {
        case 0: Bm = Wq; C = d_Q; mode = 1; break;
        case 1: Bm = Wk; C = d_K; mode = 0; break;
        case 2: Bm = Wv; C = d_V; mode = 0; break;
        default: Bm = Wg; C = d_G; mode = 2; break;
    }
    int m0 = blockIdx.x * 64, n0 = blockIdx.y * 64;
    float acc[4][4] = {};
    gemm_tile_64x64(d_sln, Bm, m0, n0, acc);

    int tx = threadIdx.x & 15, ty = threadIdx.x >> 4;
#pragma unroll
    for (int ii = 0; ii < 4; ii++)
#pragma unroll
        for (int jj = 0; jj < 4; jj++) {
            int mI = m0 + ty * 4 + ii, nI = n0 + tx * 4 + jj;
            float v = acc[ii][jj];
            if (mode == 1) v += bq[nI];
            if (mode == 2) v = 1.f / (1.f + __expf(-v));
            C[mI * 256 + nI] = v;
        }
}

// ---------------- Kernel 3: LayerNorm(z) fused with @Wb -> Bt[i][h][j] ----------------
// grid (1024, 8), 256 threads = 8 warps; each warp handles 16 (i,j) pairs.
// Folded multi-value butterfly for the 8-head reduce (9 shuffles), prefetched loads,
// results staged in smem and written as coalesced 512B rows.
__global__ __launch_bounds__(256) void zln_bias_kernel(const float* __restrict__ z,
                                                       const float* __restrict__ gz,
                                                       const float* __restrict__ bz,
                                                       const float* __restrict__ Wb) {
    __shared__ float Wbs[CZ * NH];   // [c][h]
    __shared__ float gzs[CZ], bzs[CZ];
    __shared__ float sOut[NH * 132]; // padded stride 132 (conflict-free, float4-aligned)

    int t = threadIdx.x;
    for (int idx = t; idx < CZ * NH; idx += 256) Wbs[idx] = Wb[idx];
    if (t < CZ) { gzs[t] = gz[t]; bzs[t] = bz[t]; }
    __syncthreads();

    int warp = t >> 5, lane = t & 31;
    int i = blockIdx.x;
    int jbase = blockIdx.y * 128;
    const float* zrow = z + ((size_t)i * L + jbase + warp * 16) * CZ + lane * 4;
    // lane -> head it finally owns (bits 4,3,2)
    int head = ((lane >> 4) & 1) * 4 + ((lane >> 3) & 1) * 2 + ((lane >> 2) & 1);
    int c0 = lane * 4;
    float w0[4], w1[4], w2[4], w3[4], w4[4], w5[4], w6[4], w7[4];
#pragma unroll
    for (int c = 0; c < 4; c++) {
        const float* wr = &Wbs[(c0 + c) * NH];
        w0[c] = wr[0]; w1[c] = wr[1]; w2[c] = wr[2]; w3[c] = wr[3];
        w4[c] = wr[4]; w5[c] = wr[5]; w6[c] = wr[6]; w7[c] = wr[7];
    }
    float g4[4] = {gzs[c0], gzs[c0 + 1], gzs[c0 + 2], gzs[c0 + 3]};
    float b4[4] = {bzs[c0], bzs[c0 + 1], bzs[c0 + 2], bzs[c0 + 3]};

    float4 cur = *(const float4*)zrow;
    for (int it = 0; it < 16; it++) {
        float4 nxt = make_float4(0.f, 0.f, 0.f, 0.f);
        if (it < 15) nxt = *(const float4*)(zrow + (size_t)(it + 1) * CZ);

        float s1 = cur.x + cur.y + cur.z + cur.w;
        float s2 = fmaf(cur.x, cur.x, fmaf(cur.y, cur.y, fmaf(cur.z, cur.z, cur.w * cur.w)));
#pragma unroll
        for (int off = 16; off > 0; off >>= 1) {
            s1 += __shfl_xor_sync(0xffffffffu, s1, off);
            s2 += __shfl_xor_sync(0xffffffffu, s2, off);
        }
        float mean = s1 * (1.f / CZ);
        float var = s2 * (1.f / CZ) - mean * mean;
        float rstd = rsqrtf(var + LN_EPS);

        float zn[4];
        zn[0] = (cur.x - mean) * rstd * g4[0] + b4[0];
        zn[1] = (cur.y - mean) * rstd * g4[1] + b4[1];
        zn[2] = (cur.z - mean) * rstd * g4[2] + b4[2];
        zn[3] = (cur.w - mean) * rstd * g4[3] + b4[3];

        float a[8] = {};
#pragma unroll
        for (int c = 0; c < 4; c++) {
            a[0] = fmaf(zn[c], w0[c], a[0]);
            a[1] = fmaf(zn[c], w1[c], a[1]);
            a[2] = fmaf(zn[c], w2[c], a[2]);
            a[3] = fmaf(zn[c], w3[c], a[3]);
            a[4] = fmaf(zn[c], w4[c], a[4]);
            a[5] = fmaf(zn[c], w5[c], a[5]);
            a[6] = fmaf(zn[c], w6[c], a[6]);
            a[7] = fmaf(zn[c], w7[c], a[7]);
        }
        // folded reduce: 9 shuffles total, head value lands on its lane group
        bool hi16 = (lane & 16) != 0;
        float bb[4];
#pragma unroll
        for (int k = 0; k < 4; k++) {
            float sel = hi16 ? a[k] : a[k + 4];
            float rcv = __shfl_xor_sync(0xffffffffu, sel, 16);
            bb[k] = (hi16 ? a[k + 4] : a[k]) + rcv;
        }
        bool hi8 = (lane & 8) != 0;
        float cc[2];
#pragma unroll
        for (int k = 0; k < 2; k++) {
            float sel = hi8 ? bb[k] : bb[k + 2];
            float rcv = __shfl_xor_sync(0xffffffffu, sel, 8);
            cc[k] = (hi8 ? bb[k + 2] : bb[k]) + rcv;
        }
        bool hi4 = (lane & 4) != 0;
        {
            float sel = hi4 ? cc[0] : cc[1];
            float rcv = __shfl_xor_sync(0xffffffffu, sel, 4);
            float dd = (hi4 ? cc[1] : cc[0]) + rcv;
            dd += __shfl_xor_sync(0xffffffffu, dd, 2);
            dd += __shfl_xor_sync(0xffffffffu, dd, 1);
            if ((lane & 3) == 0) sOut[head * 132 + warp * 16 + it] = dd;
        }
        cur = nxt;
    }
    __syncthreads();

    int h = t >> 5, col = (t & 31) * 4;
    float4 v = *(const float4*)&sOut[h * 132 + col];
    *(float4*)&d_Bt[((size_t)i * NH + h) * L + jbase + col] = v;
}

// ---------------- Kernel 4a: split attention, 4 j-splits of 256 ----------------
__global__ __launch_bounds__(128) void attn_split_kernel(const int* __restrict__ mask) {
    __shared__ float Qs[32][33];
    __shared__ float Ks[64][33];
    __shared__ float Vs[64][32];
    __shared__ float Ss[32][65];
    __shared__ unsigned char ms[64];

    int t = threadIdx.x;
    int h = blockIdx.y;
    int i0 = blockIdx.x * 32;
    int split = blockIdx.z;
    int tx = t & 15, ty = t >> 4;
    int rw = t >> 2, gq = t & 3;
    int dbase = gq * 8;

    {
        int r = t >> 2, c = (t & 3) * 8;
#pragma unroll
        for (int q = 0; q < 8; q++)
            Qs[r][c + q] = d_Q[(i0 + r) * CS + h * DH + c + q] * QK_SCALE;
    }

    float m = -CUDART_INF_F, l = 0.f;
    float O[8] = {};

    for (int jt = 0; jt < 4; jt++) {
        int j0 = split * 256 + jt * 64;
        __syncthreads();
        {
            int r = t >> 1, c = (t & 1) * 16;
#pragma unroll
            for (int q = 0; q < 16; q++) {
                Ks[r][c + q] = d_K[(j0 + r) * CS + h * DH + c + q];
                Vs[r][c + q] = d_V[(j0 + r) * CS + h * DH + c + q];
            }
        }
        if (t < 64) ms[t] = (unsigned char)(mask[j0 + t] != 0);
        __syncthreads();

        float sacc[4][4] = {};
#pragma unroll 8
        for (int d = 0; d < 32; d++) {
            float a[4], bb[4];
#pragma unroll
            for (int ii = 0; ii < 4; ii++) a[ii] = Qs[ty * 4 + ii][d];
#pragma unroll
            for (int jj = 0; jj < 4; jj++) bb[jj] = Ks[tx * 4 + jj][d];
#pragma unroll
            for (int ii = 0; ii < 4; ii++)
#pragma unroll
                for (int jj = 0; jj < 4; jj++) sacc[ii][jj] = fmaf(a[ii], bb[jj], sacc[ii][jj]);
        }
#pragma unroll
        for (int ii = 0; ii < 4; ii++) {
            int iI = ty * 4 + ii;
            const float4 bv = *(const float4*)&d_Bt[(size_t)(i0 + iI) * (NH * L) + h * L + j0 + tx * 4];
            float bb4[4] = {bv.x, bv.y, bv.z, bv.w};
#pragma unroll
            for (int jj = 0; jj < 4; jj++) {
                int jl = tx * 4 + jj;
                Ss[iI][jl] = ms[jl] ? (sacc[ii][jj] + bb4[jj]) : -CUDART_INF_F;
            }
        }
        __syncthreads();

        float mx = -CUDART_INF_F;
#pragma unroll
        for (int q = 0; q < 16; q++) mx = fmaxf(mx, Ss[rw][gq * 16 + q]);
        mx = fmaxf(mx, __shfl_xor_sync(0xffffffffu, mx, 1));
        mx = fmaxf(mx, __shfl_xor_sync(0xffffffffu, mx, 2));
        float nm = fmaxf(m, mx);
        float alpha = (nm == -CUDART_INF_F) ? 1.f : __expf(m - nm);
        float ps = 0.f;
#pragma unroll
        for (int q = 0; q < 16; q++) {
            float sv = Ss[rw][gq * 16 + q];
            float p = (sv == -CUDART_INF_F) ? 0.f : __expf(sv - nm);
            Ss[rw][gq * 16 + q] = p;
            ps += p;
        }
        ps += __shfl_xor_sync(0xffffffffu, ps, 1);
        ps += __shfl_xor_sync(0xffffffffu, ps, 2);
        l = l * alpha + ps;
        m = nm;
#pragma unroll
        for (int k = 0; k < 8; k++) O[k] *= alpha;
        __syncwarp();

#pragma unroll 4
        for (int j = 0; j < 64; j++) {
            float p = Ss[rw][j];
            const float4 v0 = *(const float4*)&Vs[j][dbase];
            const float4 v1 = *(const float4*)&Vs[j][dbase + 4];
            O[0] = fmaf(p, v0.x, O[0]);
            O[1] = fmaf(p, v0.y, O[1]);
            O[2] = fmaf(p, v0.z, O[2]);
            O[3] = fmaf(p, v0.w, O[3]);
            O[4] = fmaf(p, v1.x, O[4]);
            O[5] = fmaf(p, v1.y, O[5]);
            O[6] = fmaf(p, v1.z, O[6]);
            O[7] = fmaf(p, v1.w, O[7]);
        }
        __syncwarp();
    }

    int row = i0 + rw;
    int base = (((split * NH + h) * L) + row) * DH + dbase;
#pragma unroll
    for (int q = 0; q < 8; q++) d_pO[base + q] = O[q];
    if (gq == 0) d_pml[((split * NH + h) * L) + row] = make_float2(m, l);
}

// ---------------- Kernel 4b: combine splits, apply 1/l and G gate ----------------
__global__ __launch_bounds__(256) void attn_combine_kernel() {
    int t = threadIdx.x;
    int i = blockIdx.x;
    int h = t >> 5, lane = t & 31;

    float2 ml[NSPLIT];
    float mx = -CUDART_INF_F;
#pragma unroll
    for (int s = 0; s < NSPLIT; s++) {
        ml[s] = d_pml[((s * NH + h) * L) + i];
        mx = fmaxf(mx, ml[s].x);
    }
    float lsum = 0.f, o = 0.f;
#pragma unroll
    for (int s = 0; s < NSPLIT; s++) {
        float w = (ml[s].x == -CUDART_INF_F) ? 0.f : __expf(ml[s].x - mx);
        lsum = fmaf(ml[s].y, w, lsum);
        o = fmaf(d_pO[(((s * NH + h) * L) + i) * DH + lane], w, o);
    }
    float rl = (lsum > 0.f) ? (1.f / lsum) : 0.f;
    int base = i * CS + h * DH + lane;
    d_AO[base] = o * rl * d_G[base];
}

// ---------------- Kernel 5: ds = (G*out) @ Wo * mask ----------------
__global__ __launch_bounds__(256) void gemm_out_kernel(const float* __restrict__ Wo,
                                                       const int* __restrict__ mask,
                                                       float* __restrict__ out) {
    int m0 = blockIdx.x * 64, n0 = blockIdx.y * 64;
    float acc[4][4] = {};
    gemm_tile_64x64(d_AO, Wo, m0, n0, acc);

    int tx = threadIdx.x & 15, ty = threadIdx.x >> 4;
#pragma unroll
    for (int ii = 0; ii < 4; ii++) {
        int mI = m0 + ty * 4 + ii;
        float mk = (mask[mI] != 0) ? 1.f : 0.f;
#pragma unroll
        for (int jj = 0; jj < 4; jj++) {
            int nI = n0 + tx * 4 + jj;
            out[mI * 256 + nI] = acc[ii][jj] * mk;
        }
    }
}

// ---------------- launch ----------------
extern "C" void kernel_launch(void* const* d_in, const int* in_sizes, int n_in,
                              void* d_out, int out_size) {
    const float* s = (const float*)d_in[0];
    const float* z = (const float*)d_in[1];
    const int* res_mask = (const int*)d_in[2];
    const float* g_s = (const float*)d_in[3];
    const float* b_s = (const float*)d_in[4];
    const float* g_z = (const float*)d_in[5];
    const float* b_z = (const float*)d_in[6];
    const float* Wq = (const float*)d_in[7];
    const float* bq = (const float*)d_in[8];
    const float* Wk = (const float*)d_in[9];
    const float* Wv = (const float*)d_in[10];
    const float* Wb = (const float*)d_in[11];
    const float* Wg = (const float*)d_in[12];
    const float* Wo = (const float*)d_in[13];
    float* out = (float*)d_out;

    ln_s_kernel<<<L, 256>>>(s, g_s, b_s);
    gemm_qkvg_kernel<<<dim3(16, 4, 4), 256>>>(Wq, bq, Wk, Wv, Wg);
    zln_bias_kernel<<<dim3(L, 8), 256>>>(z, g_z, b_z, Wb);
    attn_split_kernel<<<dim3(32, 8, NSPLIT), 128>>>(res_mask);
    attn_combine_kernel<<<L, 256>>>();
    gemm_out_kernel<<<dim3(16, 4), 256>>>(Wo, res_mask, out);
}